// round 3
// baseline (speedup 1.0000x reference)
#include <cuda_runtime.h>
#include <cstddef>

// Problem constants
#define BB   8
#define CC   62
#define CIN  64
#define GG   26
#define G3   17576          // 26^3
#define G2   676            // 26^2
#define NPT  32768
#define HH   1024
#define YSZ  (BB*3*NPT)     // 786432, offset of reg block in output

typedef unsigned long long u64;

// ---------------- scratch (no allocations allowed) ----------------
__device__ float g_csum[BB * G3];
__device__ int   g_counts[BB * G3];
__device__ int   g_offs[BB * G3];
__device__ int   g_sorted[BB * NPT];

// ---------------- packed f32x2 FMA ----------------
__device__ __forceinline__ u64 fma2(u64 a, u64 b, u64 c) {
    u64 d;
    asm("fma.rn.f32x2 %0, %1, %2, %3;" : "=l"(d) : "l"(a), "l"(b), "l"(c));
    return d;
}

// ---------------- kernel 0: zero histogram ----------------
__global__ void k_zero() {
    int i = blockIdx.x * blockDim.x + threadIdx.x;
    if (i < BB * G3) g_counts[i] = 0;
}

// ---------------- kernel 1: XLA:CPU ReduceWindowRewriter-exact cumsum ----------------
// jnp.cumsum on CPU lowers to reduce_window; XLA:CPU's ReduceWindowRewriter
// (base_length=16) rewrites it into a blocked hierarchical scan:
//   - contiguous 16-element blocks, serial scan within block
//   - block totals scanned recursively (17576 -> 1099 -> 69 -> 5, then naive serial)
//   - element = (in-block serial prefix) + (prev-blocks prefix), single add (block0 adds +0.0f)
#define NB1 1099   // ceil(17576/16)
#define NB2 69     // ceil(1099/16)
#define NB3 5      // ceil(69/16), <= 16 -> naive serial

__global__ __launch_bounds__(1024) void k_cumsum_rw(const float* __restrict__ dens) {
    __shared__ float T1[NB1];
    __shared__ float T2[NB2];
    __shared__ float T3[NB3];
    const int b = blockIdx.x;
    const int tid = threadIdx.x;
    const float* d = dens + (size_t)b * G3;

    // level-0 block sums (serial within block, left to right)
    for (int j = tid; j < NB1; j += 1024) {
        const int s0 = j * 16;
        const int e0 = min(s0 + 16, G3);
        float s = 0.f;
        for (int i = s0; i < e0; ++i) s += d[i];
        T1[j] = s;
    }
    __syncthreads();
    // level-1 block sums
    if (tid < NB2) {
        const int s1 = tid * 16;
        const int e1 = min(s1 + 16, NB1);
        float s = 0.f;
        for (int i = s1; i < e1; ++i) s += T1[i];
        T2[tid] = s;
    }
    __syncthreads();
    // level-2 block sums, cs3 (naive serial), cs2 (in place over T2)
    if (tid == 0) {
        for (int j = 0; j < NB3; ++j) {
            const int s2 = j * 16;
            const int e2 = min(s2 + 16, NB2);
            float s = 0.f;
            for (int i = s2; i < e2; ++i) s += T2[i];
            T3[j] = s;
        }
        float s = 0.f;
        for (int j = 0; j < NB3; ++j) { s += T3[j]; T3[j] = s; }
        for (int j2 = 0; j2 < NB3; ++j2) {
            const float P = (j2 > 0) ? T3[j2 - 1] : 0.0f;
            float sr = 0.f;
            const int s2 = j2 * 16, e2 = min(j2 * 16 + 16, NB2);
            for (int i = s2; i < e2; ++i) {
                sr += T2[i];
                T2[i] = sr + P;
            }
        }
    }
    __syncthreads();
    // cs1 in place over T1 (one thread per level-1 chunk)
    if (tid < NB2) {
        const float P = (tid > 0) ? T2[tid - 1] : 0.0f;
        float sr = 0.f;
        const int s1 = tid * 16, e1 = min(tid * 16 + 16, NB1);
        for (int i = s1; i < e1; ++i) {
            sr += T1[i];
            T1[i] = sr + P;
        }
    }
    __syncthreads();
    // cs0 -> g_csum (one thread per level-0 chunk)
    float* cs = g_csum + (size_t)b * G3;
    for (int j = tid; j < NB1; j += 1024) {
        const float P = (j > 0) ? T1[j - 1] : 0.0f;
        float sr = 0.f;
        const int s0 = j * 16, e0 = min(j * 16 + 16, G3);
        for (int i = s0; i < e0; ++i) {
            sr += d[i];
            cs[i] = sr + P;
        }
    }
}

// ---------------- kernel 2: sample -> histogram ----------------
__global__ void k_sample(const float* __restrict__ u) {
    int g = blockIdx.x * blockDim.x + threadIdx.x;
    if (g >= BB * NPT) return;
    int b = g >> 15;  // /32768
    const float* cs = g_csum + (size_t)b * G3;
    float total = cs[G3 - 1];
    float t = u[g] * total;
    // searchsorted side='right': first index with cs[idx] > t
    int lo = 0, hi = G3;
    while (lo < hi) {
        int mid = (lo + hi) >> 1;
        if (cs[mid] <= t) lo = mid + 1; else hi = mid;
    }
    int idx = lo;
    if (idx > G3 - 1) idx = G3 - 1;
    atomicAdd(&g_counts[b * G3 + idx], 1);
}

// ---------------- kernel 3: exclusive scan + run-length emit (counting sort) ----------------
__global__ void k_scanfill() {
    const int b = blockIdx.x;
    const int* cnt = g_counts + b * G3;
    int* offs = g_offs + b * G3;
    int* srt  = g_sorted + b * NPT;

    __shared__ int wsum[32];
    __shared__ int s_carry;
    const int tid = threadIdx.x;
    const int lane = tid & 31, wid = tid >> 5;
    if (tid == 0) s_carry = 0;
    __syncthreads();

    const int nchunk = (G3 + 1023) / 1024;  // 18
    for (int chunk = 0; chunk < nchunk; ++chunk) {
        int i = chunk * 1024 + tid;
        int v = (i < G3) ? cnt[i] : 0;
        int x = v;
        #pragma unroll
        for (int d = 1; d < 32; d <<= 1) {
            int y = __shfl_up_sync(0xffffffffu, x, d);
            if (lane >= d) x += y;
        }
        if (lane == 31) wsum[wid] = x;
        __syncthreads();
        if (wid == 0) {
            int s = wsum[lane];
            #pragma unroll
            for (int d = 1; d < 32; d <<= 1) {
                int y = __shfl_up_sync(0xffffffffu, s, d);
                if (lane >= d) s += y;
            }
            wsum[lane] = s;
        }
        __syncthreads();
        int base = s_carry;
        int incl = x + (wid ? wsum[wid - 1] : 0);
        if (i < G3) offs[i] = base + incl - v;
        __syncthreads();
        if (tid == 1023) s_carry = base + incl;
        // next loop's syncthreads orders this write before reads
    }
    __syncthreads();

    // emit sorted values: bin i repeated cnt[i] times
    for (int i = tid; i < G3; i += 1024) {
        int off = offs[i];
        int c = cnt[i];
        for (int r = 0; r < c; ++r) srt[off + r] = i;
    }
}

// ---------------- kernel 4: fused gather + MLP + epilogue ----------------
// Block: 256 threads, 128 points, 16 passes of 64 h-rows.
// Thread tile: 8 h (rowt + 8*i) x 4 points (col + 32*j), f32x2 packed over k-pairs.
#define PITCH 68
#define SMEM_FLOATS (64*PITCH + 128*PITCH + 1024 + 3072 + 3072)
#define SMEM_BYTES  (SMEM_FLOATS*4 + 128*4)

__global__ __launch_bounds__(256) void k_mlp(
    const float* __restrict__ x, const float* __restrict__ rnd,
    const float* __restrict__ W1, const float* __restrict__ b1,
    const float* __restrict__ W2, const float* __restrict__ b2,
    float* __restrict__ out)
{
    extern __shared__ float sm[];
    float* sW   = sm;                      // 64*68 = 4352
    float* sV   = sW + 64 * PITCH;         // 128*68 = 8704
    float* sB1  = sV + 128 * PITCH;        // 1024
    float* sW2  = sB1 + 1024;              // 3072
    float* sRed = sW2 + 3072;              // 24*128 = 3072
    int*   sIdx = (int*)(sRed + 3072);     // 128

    const int tid = threadIdx.x;
    const int b = blockIdx.y;
    const int j0 = blockIdx.x * 128;

    if (tid < 128) sIdx[tid] = g_sorted[b * NPT + j0 + tid];
    #pragma unroll
    for (int it = 0; it < 4; ++it) sB1[it * 256 + tid] = b1[it * 256 + tid];
    #pragma unroll
    for (int it = 0; it < 12; ++it) sW2[it * 256 + tid] = W2[it * 256 + tid];
    __syncthreads();

    // gather V: [p][c], channels 0..61 from x, 62..63 from rnd
    {
        const int p = tid & 127;
        const int c0 = tid >> 7;          // 0 or 1
        const int gidx = sIdx[p];
        const float* xb = x + (size_t)b * CC * G3 + gidx;
        for (int c = c0; c < CC; c += 2)
            sV[p * PITCH + c] = xb[(size_t)c * G3];
        sV[p * PITCH + 62 + c0] = rnd[((size_t)b * 2 + c0) * NPT + j0 + p] * 2.0f - 1.0f;
    }

    const int col = tid & 31;
    const int rowt = tid >> 5;
    float acc0[4] = {0,0,0,0}, acc1[4] = {0,0,0,0}, acc2[4] = {0,0,0,0};

    for (int pass = 0; pass < 16; ++pass) {
        __syncthreads();
        // stage W1 tile: rows pass*64 .. pass*64+63
        #pragma unroll
        for (int it = 0; it < 4; ++it) {
            int lin = it * 256 + tid;          // 0..1023 float4s
            int hl = lin >> 4;
            int c4 = (lin & 15) << 2;
            const float4 w = *reinterpret_cast<const float4*>(
                W1 + (((size_t)(pass * 64 + hl)) << 6) + c4);
            float2* d = reinterpret_cast<float2*>(&sW[hl * PITCH + c4]);
            d[0] = make_float2(w.x, w.y);
            d[1] = make_float2(w.z, w.w);
        }
        __syncthreads();

        u64 s2[8][4];
        #pragma unroll
        for (int i = 0; i < 8; ++i)
            #pragma unroll
            for (int j = 0; j < 4; ++j) s2[i][j] = 0ull;

        #pragma unroll 4
        for (int k2 = 0; k2 < 16; ++k2) {    // 4 k per iter (2 f32x2 pairs)
            ulonglong2 vv[4];
            #pragma unroll
            for (int j = 0; j < 4; ++j)
                vv[j] = *reinterpret_cast<const ulonglong2*>(
                    &sV[(col + 32 * j) * PITCH + (k2 << 2)]);
            #pragma unroll
            for (int i = 0; i < 8; ++i) {
                const ulonglong2 wv = *reinterpret_cast<const ulonglong2*>(
                    &sW[(rowt + 8 * i) * PITCH + (k2 << 2)]);
                #pragma unroll
                for (int j = 0; j < 4; ++j) {
                    s2[i][j] = fma2(wv.x, vv[j].x, s2[i][j]);
                    s2[i][j] = fma2(wv.y, vv[j].y, s2[i][j]);
                }
            }
        }

        // relu + fold into 3 outputs
        #pragma unroll
        for (int i = 0; i < 8; ++i) {
            const int h = pass * 64 + rowt + 8 * i;
            const float bb = sB1[h];
            const float w20 = sW2[h], w21 = sW2[1024 + h], w22 = sW2[2048 + h];
            #pragma unroll
            for (int j = 0; j < 4; ++j) {
                float2 f = *reinterpret_cast<float2*>(&s2[i][j]);
                float s = f.x + f.y + bb;
                s = fmaxf(s, 0.0f);
                acc0[j] = fmaf(w20, s, acc0[j]);
                acc1[j] = fmaf(w21, s, acc1[j]);
                acc2[j] = fmaf(w22, s, acc2[j]);
            }
        }
    }

    // cross-row reduction (8 partials per point per output)
    __syncthreads();
    #pragma unroll
    for (int j = 0; j < 4; ++j) {
        const int p = col + 32 * j;
        sRed[(rowt * 3 + 0) * 128 + p] = acc0[j];
        sRed[(rowt * 3 + 1) * 128 + p] = acc1[j];
        sRed[(rowt * 3 + 2) * 128 + p] = acc2[j];
    }
    __syncthreads();
    if (tid < 128) {
        const int p = tid;
        float v0 = 0.f, v1 = 0.f, v2 = 0.f;
        #pragma unroll
        for (int r = 0; r < 8; ++r) {
            v0 += sRed[(r * 3 + 0) * 128 + p];
            v1 += sRed[(r * 3 + 1) * 128 + p];
            v2 += sRed[(r * 3 + 2) * 128 + p];
        }
        v0 += __ldg(&b2[0]); v1 += __ldg(&b2[1]); v2 += __ldg(&b2[2]);
        const float nrm = sqrtf(v0 * v0 + v1 * v1 + v2 * v2);
        const float rg = fmaxf(nrm - 0.06661733875264912f, 0.0f);  // sqrt(3)/26
        const int gidx = sIdx[p];
        const int ix = gidx / G2;
        const int rem = gidx - ix * G2;
        const int iy = rem / GG;
        const int iz = rem - iy * GG;
        const float ox = ((float)ix + 0.5f) * 2.0f / 26.0f - 1.0f;
        const float oy = ((float)iy + 0.5f) * 2.0f / 26.0f - 1.0f;
        const float oz = ((float)iz + 0.5f) * 2.0f / 26.0f - 1.0f;
        const size_t j = (size_t)j0 + p;
        out[((size_t)b * 3 + 0) * NPT + j] = v0 + ox;
        out[((size_t)b * 3 + 1) * NPT + j] = v1 + oy;
        out[((size_t)b * 3 + 2) * NPT + j] = v2 + oz;
        out[(size_t)YSZ + (size_t)b * NPT + j] = rg;
    }
}

// ---------------- launch ----------------
extern "C" void kernel_launch(void* const* d_in, const int* in_sizes, int n_in,
                              void* d_out, int out_size) {
    const float* x    = (const float*)d_in[0];
    const float* dens = (const float*)d_in[1];
    const float* rnd  = (const float*)d_in[2];
    const float* u    = (const float*)d_in[3];
    const float* W1   = (const float*)d_in[4];
    const float* b1   = (const float*)d_in[5];
    const float* W2   = (const float*)d_in[6];
    const float* b2   = (const float*)d_in[7];
    float* out = (float*)d_out;

    cudaFuncSetAttribute(k_mlp, cudaFuncAttributeMaxDynamicSharedMemorySize, SMEM_BYTES);

    k_zero<<<(BB * G3 + 1023) / 1024, 1024>>>();
    k_cumsum_rw<<<BB, 1024>>>(dens);
    k_sample<<<(BB * NPT + 255) / 256, 256>>>(u);
    k_scanfill<<<BB, 1024>>>();
    dim3 grid(NPT / 128, BB);
    k_mlp<<<grid, 256, SMEM_BYTES>>>(x, rnd, W1, b1, W2, b2, out);
}